// round 11
// baseline (speedup 1.0000x reference)
#include <cuda_runtime.h>

// ---------------------------------------------------------------------------
// 2-layer KAN (1 -> 8 -> 1) == scalar function out = f(x).
// SINGLE kernel, zero inter-block communication:
//   512 blocks x 288 threads. Threads 0..255 own one float4 of x each
//   (512*256 = 131072 = n4). All 288 threads cooperate in the build:
//   each of threads 0..258 does exactly ONE exact node eval (no serial
//   2-eval tail), rebuilding the full N=256-interval piecewise-cubic LUT of
//   f on [-8,8) (h=1/16 exact) in shared memory. Then threads 0..255 do
//   k=floor((x+8)*16), one LDS.128 + Horner per element.
// Exact fallback (same smem tables) for |x|>=8 — never hit for N(0,1).
// x loads issued first so DRAM latency hides under the build phase.
// ---------------------------------------------------------------------------

#define LUT_N    256
#define LUT_INVH 16.0f          // 1/h, exact
#define LUT_H    (1.0f / 16.0f) // h,   exact
#define LUT_OFS  128.0f         // 8*16, exact
#define NODES    259            // node indices -1..257
#define TPB      288            // 9 warps

__device__ __forceinline__ float silu_f(float x) {
    return x * __fdividef(1.0f, 1.0f + __expf(-x));
}

__device__ __forceinline__ void spline_basis(float s, float jf, float* b) {
    const float c6 = 1.0f / 6.0f;
    float t = s - jf;
    float u = 1.0f - t;
    float t2 = t * t, t3 = t2 * t;
    b[0] = u * u * u * c6;
    b[1] = (3.0f * t3 - 6.0f * t2 + 4.0f) * c6;
    b[2] = (-3.0f * t3 + 3.0f * t2 + 3.0f * t + 1.0f) * c6;
    b[3] = t3 * c6;
}

// Exact KAN eval from prescaled zero-padded smem tables (no inner bounds
// checks: row/col = spline index + 3, pads are zero == clipped bases).
__device__ __forceinline__ float kan_eval_smem(
    float x,
    const float (*s_w1t)[8],      // [14][8]: row r -> ri=r-3, prescaled sc1
    const float (*s_w2)[16],      // [8][16]: col c -> ri=c-3, prescaled sc2
    const float* s_bw1, const float* s_bw2)
{
    float si = silu_f(x);
    float h[8];
    #pragma unroll
    for (int o = 0; o < 8; o++) h[o] = si * s_bw1[o];

    float s  = (x + 2.2f) * 2.5f;
    float jf = floorf(s);
    int j = (int)jf;
    if (j >= 0 && j <= 10) {
        float b[4];
        spline_basis(s, jf, b);
        #pragma unroll
        for (int m = 0; m < 4; m++) {
            const float* row = s_w1t[j + m];   // (j-3+m)+3 in [0,13]
            float bm = b[m];
            #pragma unroll
            for (int o = 0; o < 8; o++) h[o] = fmaf(bm, row[o], h[o]);
        }
    }

    float acc = 0.0f;
    #pragma unroll
    for (int i = 0; i < 8; i++) {
        float hv = h[i];
        acc += silu_f(hv) * s_bw2[i];
        float s2  = (hv + 2.2f) * 2.5f;
        float jf2 = floorf(s2);
        int j2 = (int)jf2;
        if (j2 >= 0 && j2 <= 10) {
            float b[4];
            spline_basis(s2, jf2, b);
            const float* row = s_w2[i];
            #pragma unroll
            for (int m = 0; m < 4; m++)
                acc = fmaf(b[m], row[j2 + m], acc);   // col in [0,13]
        }
    }
    return acc;
}

__global__ __launch_bounds__(TPB)
void kan_fused_kernel(const float4* __restrict__ xv, float4* __restrict__ outv,
                      const float* __restrict__ bw1, const float* __restrict__ sw1,
                      const float* __restrict__ sc1, const float* __restrict__ bw2,
                      const float* __restrict__ sw2, const float* __restrict__ sc2,
                      int n4)
{
    __shared__ __align__(16) float4 s_lut[LUT_N];
    __shared__ float s_y[NODES];
    __shared__ __align__(16) float s_w1t[14][8];
    __shared__ __align__(16) float s_w2[8][16];
    __shared__ float s_bw1[8], s_bw2[8];

    int tid = threadIdx.x;
    int idx = blockIdx.x * 256 + tid;          // only tid<256 evaluates

    // 1) Issue the x load immediately (DRAM latency hides under the build).
    bool valid = (tid < 256) && (idx < n4);
    float4 xin = valid ? xv[idx] : make_float4(0.f, 0.f, 0.f, 0.f);

    // 2) Stage prescaled, zero-padded weight tables (one pass over 288 thr).
    if (tid < 112) {                       // s_w1t: 14 rows x 8 units
        int r = tid >> 3, o = tid & 7, ri = r - 3;
        s_w1t[r][o] = (ri >= 0 && ri < 8) ? __ldg(sw1 + o * 8 + ri) * __ldg(sc1 + o)
                                          : 0.0f;
    } else if (tid < 240) {                // s_w2: 8 units x 16 cols
        int q = tid - 112, i = q >> 4, c = q & 15, ri = c - 3;
        s_w2[i][c] = (ri >= 0 && ri < 8) ? __ldg(sw2 + i * 8 + ri) * __ldg(sc2 + i)
                                         : 0.0f;
    } else if (tid < 248) {
        s_bw1[tid - 240] = __ldg(bw1 + (tid - 240));
    } else if (tid < 256) {
        s_bw2[tid - 248] = __ldg(bw2 + (tid - 248));
    }
    __syncthreads();

    // 3) Build: exactly ONE node eval per thread (tid 0..258 -> node tid-1).
    if (tid < NODES) {
        float xn = fmaf((float)(tid - 1), LUT_H, -8.0f);   // exact grid node
        s_y[tid] = kan_eval_smem(xn, s_w1t, s_w2, s_bw1, s_bw2);
    }
    __syncthreads();

    // 4) Coefficients: interval k=tid from nodes k-1..k+2 = s_y[tid..tid+3].
    if (tid < LUT_N) {
        float y0 = s_y[tid], y1 = s_y[tid + 1];
        float y2 = s_y[tid + 2], y3 = s_y[tid + 3];
        // Lagrange cubic through (u=-1,y0),(0,y1),(1,y2),(2,y3):
        float c0 = y1;
        float c1 = -y0 * (1.0f/3.0f) - 0.5f * y1 + y2 - y3 * (1.0f/6.0f);
        float c2 =  0.5f * y0 - y1 + 0.5f * y2;
        float c3 = (y3 - y0) * (1.0f/6.0f) + 0.5f * (y1 - y2);
        s_lut[tid] = make_float4(c0, c1, c2, c3);
    }
    __syncthreads();

    // 5) Evaluate 4 elements: one random LDS.128 + Horner each.
    if (valid) {
        float xi[4] = {xin.x, xin.y, xin.z, xin.w};
        float r[4];
        bool oor_any = false;
        unsigned oor_mask = 0;

        #pragma unroll
        for (int e = 0; e < 4; e++) {
            float x = xi[e];
            float s = fmaf(x, LUT_INVH, LUT_OFS);
            float kf = floorf(s);
            int k = (int)kf;
            bool oo = (k < 0) | (k >= LUT_N);
            oor_any |= oo;
            if (oo) oor_mask |= 1u << e;
            k = max(0, min(LUT_N - 1, k));
            float u = fmaf(x, LUT_INVH, LUT_OFS - (float)k);
            float4 cf = s_lut[k];
            r[e] = fmaf(fmaf(fmaf(cf.w, u, cf.z), u, cf.y), u, cf.x);
        }

        if (oor_any) {   // essentially never taken for N(0,1) inputs
            #pragma unroll
            for (int e = 0; e < 4; e++)
                if (oor_mask & (1u << e))
                    r[e] = kan_eval_smem(xi[e], s_w1t, s_w2, s_bw1, s_bw2);
        }

        outv[idx] = make_float4(r[0], r[1], r[2], r[3]);
    }
}

extern "C" void kernel_launch(void* const* d_in, const int* in_sizes, int n_in,
                              void* d_out, int out_size) {
    const float* x   = (const float*)d_in[0];
    const float* bw1 = (const float*)d_in[1];
    const float* sw1 = (const float*)d_in[2];
    const float* sc1 = (const float*)d_in[3];
    const float* bw2 = (const float*)d_in[4];
    const float* sw2 = (const float*)d_in[5];
    const float* sc2 = (const float*)d_in[6];

    int n  = in_sizes[0];   // 524288
    int n4 = n / 4;         // 131072

    int blocks = (n4 + 255) / 256;   // 512 blocks, 1 float4 per eval thread
    kan_fused_kernel<<<blocks, TPB>>>((const float4*)x, (float4*)d_out,
                                      bw1, sw1, sc1, bw2, sw2, sc2, n4);
}